// round 1
// baseline (speedup 1.0000x reference)
#include <cuda_runtime.h>
#include <math.h>

#define B_  64
#define T_  512
#define F_  3072
#define I_  1024
#define H_  1024
#define G4  4096
#define NC  22
#define M_  (B_*T_)   /* 32768 */

// Scratch (allocation-free: __device__ globals)
__device__ float g_x[M_ * I_];            // 128 MB: relu(pre) output, [m=b*T+t][1024]
__device__ float g_gx[T_ * B_ * G4];      // 512 MB: gate input precompute, [t][b][4096]
__device__ float g_h[2][B_ * H_];         // double-buffered hidden state
__device__ float g_c[B_ * H_];            // cell state

__global__ void init_state() {
    int i = blockIdx.x * blockDim.x + threadIdx.x;
    if (i < B_ * H_) { g_h[0][i] = 0.f; g_c[i] = 0.f; }
}

// ---------------------------------------------------------------------------
// Tiled fp32 NT-GEMM: C[m,n] = sum_k A[m,k] * W[n,k] (+bias, +relu / remap)
// BM=128, BN=64, BK=16, 256 threads, 8x4 micro-tile per thread.
// MODE 0: A=feat (K=3072), C=g_x, +b_pre, ReLU, plain [m][n] store
// MODE 1: A=g_x  (K=1024), C=g_gx, +b_ih+b_hh, store remapped [t][b][n]
// ---------------------------------------------------------------------------
template<int K, int MODE>
__global__ __launch_bounds__(256) void gemm_nt(const float* __restrict__ Ain,
                                               const float* __restrict__ W,
                                               const float* __restrict__ bias0,
                                               const float* __restrict__ bias1)
{
    const float* __restrict__ A = (MODE == 0) ? Ain : g_x;

    __shared__ float As[16][128];
    __shared__ float Bs[16][64];

    int tid = threadIdx.x;
    int tx = tid & 15, ty = tid >> 4;
    int m0 = blockIdx.y * 128;
    int n0 = blockIdx.x * 64;

    float acc[8][4];
#pragma unroll
    for (int i = 0; i < 8; i++)
#pragma unroll
        for (int j = 0; j < 4; j++) acc[i][j] = 0.f;

    int kq = (tid & 3) << 2;           // 0,4,8,12

    for (int k0 = 0; k0 < K; k0 += 16) {
#pragma unroll
        for (int r = 0; r < 2; r++) {
            int m = (tid >> 2) + r * 64;                  // 0..127
            float4 v = *reinterpret_cast<const float4*>(
                &A[(size_t)(m0 + m) * K + k0 + kq]);
            As[kq + 0][m] = v.x; As[kq + 1][m] = v.y;
            As[kq + 2][m] = v.z; As[kq + 3][m] = v.w;
        }
        {
            int n = tid >> 2;                             // 0..63
            float4 v = *reinterpret_cast<const float4*>(
                &W[(size_t)(n0 + n) * K + k0 + kq]);
            Bs[kq + 0][n] = v.x; Bs[kq + 1][n] = v.y;
            Bs[kq + 2][n] = v.z; Bs[kq + 3][n] = v.w;
        }
        __syncthreads();
#pragma unroll
        for (int kk = 0; kk < 16; kk++) {
            float a[8], b[4];
#pragma unroll
            for (int i = 0; i < 8; i++) a[i] = As[kk][ty + i * 16];
#pragma unroll
            for (int j = 0; j < 4; j++) b[j] = Bs[kk][tx + j * 16];
#pragma unroll
            for (int i = 0; i < 8; i++)
#pragma unroll
                for (int j = 0; j < 4; j++)
                    acc[i][j] = fmaf(a[i], b[j], acc[i][j]);
        }
        __syncthreads();
    }

#pragma unroll
    for (int i = 0; i < 8; i++) {
        int m = m0 + ty + i * 16;
#pragma unroll
        for (int j = 0; j < 4; j++) {
            int n = n0 + tx + j * 16;
            float v = acc[i][j];
            if (MODE == 0) {
                v += bias0[n];
                v = fmaxf(v, 0.f);
                g_x[(size_t)m * I_ + n] = v;
            } else {
                v += bias0[n] + bias1[n];
                int bb = m >> 9;          // m = b*512 + t
                int tt = m & 511;
                g_gx[((size_t)tt * B_ + bb) * G4 + n] = v;
            }
        }
    }
}

// ---------------------------------------------------------------------------
// Recurrent step
// ---------------------------------------------------------------------------
__device__ __forceinline__ float sigf(float x) { return 1.f / (1.f + expf(-x)); }

// classifier for one timestep: scores[b, t, :] = h[b,:] @ W_cls^T + b_cls
// 4 blocks (cb=0..3), each handles 16 batches; warp per output, float4 dots.
__device__ __forceinline__ void classifier(const float* __restrict__ h,
                                           const float* __restrict__ Wc,
                                           const float* __restrict__ bc,
                                           float* __restrict__ out,
                                           int t, int cb)
{
    int tid = threadIdx.x;
    int warp = tid >> 5, lane = tid & 31;
    for (int o = warp; o < 16 * NC; o += 8) {
        int bb  = cb * 16 + o / NC;
        int cls = o % NC;
        const float4* hr = reinterpret_cast<const float4*>(h + bb * H_);
        const float4* wr = reinterpret_cast<const float4*>(Wc + cls * H_);
        float s = 0.f;
        for (int k = lane; k < H_ / 4; k += 32) {
            float4 a = hr[k], b = wr[k];
            s += a.x * b.x + a.y * b.y + a.z * b.z + a.w * b.w;
        }
#pragma unroll
        for (int off = 16; off; off >>= 1)
            s += __shfl_xor_sync(0xffffffffu, s, off);
        if (lane == 0)
            out[((size_t)bb * T_ + t) * NC + cls] = s + bc[cls];
    }
}

// One LSTM step. Blocks 0..127: each owns h-slice [s0, s0+8) across ALL FOUR
// gates (64x32 GEMM slice) -> full fused cell update for its slice.
// Blocks 128..131: classifier for step t-1 (h double-buffered so no race).
__global__ __launch_bounds__(256) void lstm_step(const float* __restrict__ W_hh,
                                                 const float* __restrict__ W_cls,
                                                 const float* __restrict__ b_cls,
                                                 float* __restrict__ out, int t)
{
    const float* __restrict__ h_in = g_h[t & 1];
    float* __restrict__ h_out      = g_h[(t + 1) & 1];

    if (blockIdx.x >= 128) {
        if (t > 0) classifier(h_in, W_cls, b_cls, out, t - 1, blockIdx.x - 128);
        return;
    }

    __shared__ float Hs[16][64];
    __shared__ float Ws[16][32];
    __shared__ float gsm[64][33];

    int tid = threadIdx.x;
    int tx = tid & 15, ty = tid >> 4;
    int s0 = blockIdx.x * 8;

    float acc[4][2] = {{0.f,0.f},{0.f,0.f},{0.f,0.f},{0.f,0.f}};
    int kq = (tid & 3) << 2;
    int cj = tid >> 2;                                   // 0..63 (W loader uses <32)
    int wn = ((cj >> 3) << 10) + s0 + (cj & 7);          // gate*1024 + s0 + sub

    for (int k0 = 0; k0 < H_; k0 += 16) {
        {
            int m = tid >> 2;                            // 0..63
            float4 v = *reinterpret_cast<const float4*>(
                &h_in[m * H_ + k0 + kq]);
            Hs[kq + 0][m] = v.x; Hs[kq + 1][m] = v.y;
            Hs[kq + 2][m] = v.z; Hs[kq + 3][m] = v.w;
        }
        if (tid < 128) {
            float4 v = *reinterpret_cast<const float4*>(
                &W_hh[(size_t)wn * H_ + k0 + kq]);
            Ws[kq + 0][cj] = v.x; Ws[kq + 1][cj] = v.y;
            Ws[kq + 2][cj] = v.z; Ws[kq + 3][cj] = v.w;
        }
        __syncthreads();
#pragma unroll
        for (int kk = 0; kk < 16; kk++) {
            float a[4], b[2];
#pragma unroll
            for (int i = 0; i < 4; i++) a[i] = Hs[kk][ty + i * 16];
            b[0] = Ws[kk][tx];
            b[1] = Ws[kk][tx + 16];
#pragma unroll
            for (int i = 0; i < 4; i++) {
                acc[i][0] = fmaf(a[i], b[0], acc[i][0]);
                acc[i][1] = fmaf(a[i], b[1], acc[i][1]);
            }
        }
        __syncthreads();
    }

    // add precomputed gate input (biases already folded) and park in smem
    const float* __restrict__ gx_t = g_gx + (size_t)t * B_ * G4;
#pragma unroll
    for (int i = 0; i < 4; i++) {
        int b = ty + i * 16;
#pragma unroll
        for (int j = 0; j < 2; j++) {
            int c = tx + j * 16;                          // 0..31
            int n = ((c >> 3) << 10) + s0 + (c & 7);
            gsm[b][c] = acc[i][j] + gx_t[b * G4 + n];
        }
    }
    __syncthreads();

    // fused cell update for this block's slice (cols: [i f g o] x 8)
    for (int e = tid; e < 512; e += 256) {
        int b = e >> 3, hh = e & 7;
        float iv = sigf(gsm[b][hh]);
        float fv = sigf(gsm[b][8 + hh]);
        float gv = tanhf(gsm[b][16 + hh]);
        float ov = sigf(gsm[b][24 + hh]);
        int idx = b * H_ + s0 + hh;
        float c = fv * g_c[idx] + iv * gv;
        g_c[idx] = c;
        h_out[idx] = ov * tanhf(c);
    }
}

__global__ void cls_final(const float* __restrict__ W_cls,
                          const float* __restrict__ b_cls,
                          float* __restrict__ out)
{
    // after t=511, h_511 lives in g_h[(511+1)&1] = g_h[0]
    classifier(g_h[0], W_cls, b_cls, out, T_ - 1, blockIdx.x);
}

// ---------------------------------------------------------------------------
extern "C" void kernel_launch(void* const* d_in, const int* in_sizes, int n_in,
                              void* d_out, int out_size)
{
    (void)in_sizes; (void)n_in; (void)out_size;
    const float* feat  = (const float*)d_in[0];
    const float* W_pre = (const float*)d_in[1];
    const float* b_pre = (const float*)d_in[2];
    const float* W_ih  = (const float*)d_in[3];
    const float* b_ih  = (const float*)d_in[4];
    const float* W_hh  = (const float*)d_in[5];
    const float* b_hh  = (const float*)d_in[6];
    const float* W_cls = (const float*)d_in[7];
    const float* b_cls = (const float*)d_in[8];
    float* out = (float*)d_out;

    init_state<<<256, 256>>>();

    // Phase 1: x = relu(feat @ W_pre^T + b_pre)   M=32768, N=1024, K=3072
    gemm_nt<F_, 0><<<dim3(I_ / 64, M_ / 128), 256>>>(feat, W_pre, b_pre, nullptr);

    // Phase 2: gx[t][b] = x @ W_ih^T + b_ih + b_hh   M=32768, N=4096, K=1024
    gemm_nt<I_, 1><<<dim3(G4 / 64, M_ / 128), 256>>>(nullptr, W_ih, b_ih, b_hh);

    // Phase 3: recurrence (classifier for step t-1 rides in step t's kernel)
    for (int t = 0; t < T_; t++)
        lstm_step<<<132, 256>>>(W_hh, W_cls, b_cls, out, t);

    cls_final<<<4, 256>>>(W_cls, b_cls, out);
}

// round 6
// speedup vs baseline: 2.8299x; 2.8299x over previous
#include <cuda_runtime.h>
#include <cuda_bf16.h>
#include <math.h>

#define B_  64
#define T_  512
#define F_  3072
#define I_  1024
#define G4  4096
#define NC  22
#define M_  (B_*T_)     /* 32768 */
#define MP  4160        /* recurrent W'' rows: 4096 gates + 22 cls + pad */

typedef __nv_bfloat16 bf16;

// ---------------------------------------------------------------------------
// Scratch (__device__ globals; referenced ONLY from device code)
// ---------------------------------------------------------------------------
__device__ bf16 g_fHi[(size_t)M_ * F_];     // feature hi plane, k-permuted
__device__ bf16 g_fLo[(size_t)M_ * F_];
__device__ bf16 g_xHi[(size_t)M_ * I_];     // relu(pre) out, k-permuted planes
__device__ bf16 g_xLo[(size_t)M_ * I_];
__device__ float g_gx[(size_t)T_ * B_ * G4];// gate-input precompute [t][b][4096]
__device__ bf16 g_WpHi[(size_t)I_ * F_];
__device__ bf16 g_WpLo[(size_t)I_ * F_];
__device__ bf16 g_WiHi[(size_t)G4 * I_];
__device__ bf16 g_WiLo[(size_t)G4 * I_];
__device__ bf16 g_WrHi[(size_t)MP * I_];    // re-tiled [Whh;Wcls;0]
__device__ bf16 g_WrLo[(size_t)MP * I_];
__device__ bf16 g_hHi[2][B_ * I_];          // h planes, double buffered, permuted
__device__ bf16 g_hLo[2][B_ * I_];
__device__ float g_c[B_ * I_];              // cell state (fp32)

// k-permutation within a 32-group: lane quad c's 8 needed bf16 are contiguous.
__device__ __forceinline__ int perm32(int p) {
    return (((p & 7) >> 1) << 3) + ((p >> 3) << 1) + (p & 1);
}
__device__ __forceinline__ int permPair(int p) {   // p even
    return (((p & 7) >> 1) << 3) + ((p >> 3) << 1);
}

// ---------------------------------------------------------------------------
// Prep: fp32 row-major -> bf16 hi/lo planes in permuted layout.
// Destination selected by SEL *in device code* (R3-R5 bug: passing __device__
// arrays as host-side kernel args silently wrote to the host ATS shadow).
// ---------------------------------------------------------------------------
template<int SEL>
__global__ void prep_split(const float* __restrict__ src, int K)
{
    bf16* __restrict__ dHi = (SEL == 0) ? g_fHi : (SEL == 1) ? g_WpHi : g_WiHi;
    bf16* __restrict__ dLo = (SEL == 0) ? g_fLo : (SEL == 1) ? g_WpLo : g_WiLo;

    int row = blockIdx.y;
    int k = (blockIdx.x * 256 + threadIdx.x) * 2;
    float2 v = *reinterpret_cast<const float2*>(src + (size_t)row * K + k);
    int idx = (k & ~31) + permPair(k & 31);
    bf16 h0 = __float2bfloat16(v.x), h1 = __float2bfloat16(v.y);
    __nv_bfloat162 hi; hi.x = h0; hi.y = h1;
    __nv_bfloat162 lo;
    lo.x = __float2bfloat16(v.x - __bfloat162float(h0));
    lo.y = __float2bfloat16(v.y - __bfloat162float(h1));
    *reinterpret_cast<__nv_bfloat162*>(dHi + (size_t)row * K + idx) = hi;
    *reinterpret_cast<__nv_bfloat162*>(dLo + (size_t)row * K + idx) = lo;
}

// Recurrent W'': tile s (0..63) holds rows {gate g, hh = s*16+u} as g*16+u;
// tile 64 holds the 22 classifier rows (zero padded).
__global__ void prep_rec(const float* __restrict__ W_hh,
                         const float* __restrict__ W_cls)
{
    int m = blockIdx.y;
    int k = (blockIdx.x * 256 + threadIdx.x) * 2;
    float2 v = make_float2(0.f, 0.f);
    if (m < 4096) {
        int s = m >> 6, loc = m & 63, g = loc >> 4, u = loc & 15;
        v = *reinterpret_cast<const float2*>(
            W_hh + (size_t)(g * 1024 + s * 16 + u) * I_ + k);
    } else if (m < 4096 + NC) {
        v = *reinterpret_cast<const float2*>(W_cls + (size_t)(m - 4096) * I_ + k);
    }
    int idx = (k & ~31) + permPair(k & 31);
    bf16 h0 = __float2bfloat16(v.x), h1 = __float2bfloat16(v.y);
    __nv_bfloat162 hi; hi.x = h0; hi.y = h1;
    __nv_bfloat162 lo;
    lo.x = __float2bfloat16(v.x - __bfloat162float(h0));
    lo.y = __float2bfloat16(v.y - __bfloat162float(h1));
    *reinterpret_cast<__nv_bfloat162*>(g_WrHi + (size_t)m * I_ + idx) = hi;
    *reinterpret_cast<__nv_bfloat162*>(g_WrLo + (size_t)m * I_ + idx) = lo;
}

__global__ void init_state() {
    int i = blockIdx.x * blockDim.x + threadIdx.x;
    if (i < B_ * I_) {
        g_hHi[0][i] = __float2bfloat16(0.f);
        g_hLo[0][i] = __float2bfloat16(0.f);
        g_c[i] = 0.f;
    }
}

// ---------------------------------------------------------------------------
// bf16 m16n8k16 MMA, 3-term hi/lo split (layouts audited against PTX ISA)
// ---------------------------------------------------------------------------
#define MMA16816(d, a0, a1, a2, a3, b0, b1)                                   \
    asm volatile("mma.sync.aligned.m16n8k16.row.col.f32.bf16.bf16.f32 "      \
                 "{%0,%1,%2,%3}, {%4,%5,%6,%7}, {%8,%9}, {%0,%1,%2,%3};"     \
                 : "+f"(d[0]), "+f"(d[1]), "+f"(d[2]), "+f"(d[3])            \
                 : "r"(a0), "r"(a1), "r"(a2), "r"(a3), "r"(b0), "r"(b1))

#define SPLIT3(acc, A0h, A1h, A0l, A1l, Bh, Bl)                               \
    do {                                                                      \
        MMA16816(acc, A0h.x, A1h.x, A0h.y, A1h.y, Bh.x, Bh.y);                \
        MMA16816(acc, A0h.x, A1h.x, A0h.y, A1h.y, Bl.x, Bl.y);                \
        MMA16816(acc, A0l.x, A1l.x, A0l.y, A1l.y, Bh.x, Bh.y);                \
        MMA16816(acc, A0h.z, A1h.z, A0h.w, A1h.w, Bh.z, Bh.w);                \
        MMA16816(acc, A0h.z, A1h.z, A0h.w, A1h.w, Bl.z, Bl.w);                \
        MMA16816(acc, A0l.z, A1l.z, A0l.w, A1l.w, Bh.z, Bh.w);                \
    } while (0)

// ---------------------------------------------------------------------------
// Batched phase GEMMs (tensor cores, direct LDG). Tile m64 x n64, 8 warps.
// MODE 0: A=feat planes, W=W_pre planes, +b_pre, relu -> g_xHi/Lo (permuted)
// MODE 1: A=g_x planes,  W=W_ih  planes, +b_ih+b_hh  -> g_gx [t][b][n] fp32
// ---------------------------------------------------------------------------
template<int K, int MODE>
__global__ __launch_bounds__(256) void mma_gemm(const float* __restrict__ bias0,
                                                const float* __restrict__ bias1)
{
    const bf16* __restrict__ AHi = (MODE == 0) ? g_fHi : g_xHi;
    const bf16* __restrict__ ALo = (MODE == 0) ? g_fLo : g_xLo;
    const bf16* __restrict__ BHi = (MODE == 0) ? g_WpHi : g_WiHi;
    const bf16* __restrict__ BLo = (MODE == 0) ? g_WpLo : g_WiLo;

    int tid = threadIdx.x, w = tid >> 5, lane = tid & 31;
    int mw = w & 3, nw = w >> 2;
    int r = lane >> 2, c = lane & 3;
    int m0 = blockIdx.y * 64 + mw * 16;
    int n0 = blockIdx.x * 64 + nw * 32;

    const bf16* pAh = AHi + (size_t)(m0 + r) * K + c * 8;
    const bf16* pAl = ALo + (size_t)(m0 + r) * K + c * 8;
    const bf16* pBh = BHi + (size_t)(n0 + r) * K + c * 8;
    const bf16* pBl = BLo + (size_t)(n0 + r) * K + c * 8;
    const size_t A8 = (size_t)8 * K;

    float acc[4][4];
#pragma unroll
    for (int j = 0; j < 4; j++)
#pragma unroll
        for (int q = 0; q < 4; q++) acc[j][q] = 0.f;

#pragma unroll 2
    for (int q = 0; q < K / 32; q++) {
        int off = q * 32;
        uint4 ah0 = *reinterpret_cast<const uint4*>(pAh + off);
        uint4 ah1 = *reinterpret_cast<const uint4*>(pAh + A8 + off);
        uint4 al0 = *reinterpret_cast<const uint4*>(pAl + off);
        uint4 al1 = *reinterpret_cast<const uint4*>(pAl + A8 + off);
#pragma unroll
        for (int j = 0; j < 4; j++) {
            uint4 bh = *reinterpret_cast<const uint4*>(pBh + (size_t)j * A8 + off);
            uint4 bl = *reinterpret_cast<const uint4*>(pBl + (size_t)j * A8 + off);
            SPLIT3(acc[j], ah0, ah1, al0, al1, bh, bl);
        }
    }

#pragma unroll
    for (int j = 0; j < 4; j++) {
        int n = n0 + j * 8 + 2 * c;
        float bia0 = bias0[n]     + (MODE ? bias1[n]     : 0.f);
        float bia1 = bias0[n + 1] + (MODE ? bias1[n + 1] : 0.f);
        int nidx = n0 + 8 * c + 2 * j;   // permuted position (pair adjacent)
#pragma unroll
        for (int h = 0; h < 2; h++) {
            int m = m0 + r + h * 8;
            float v0 = acc[j][2 * h]     + bia0;
            float v1 = acc[j][2 * h + 1] + bia1;
            if (MODE == 0) {
                v0 = fmaxf(v0, 0.f); v1 = fmaxf(v1, 0.f);
                bf16 h0 = __float2bfloat16(v0), h1 = __float2bfloat16(v1);
                __nv_bfloat162 hi; hi.x = h0; hi.y = h1;
                __nv_bfloat162 lo;
                lo.x = __float2bfloat16(v0 - __bfloat162float(h0));
                lo.y = __float2bfloat16(v1 - __bfloat162float(h1));
                *reinterpret_cast<__nv_bfloat162*>(g_xHi + (size_t)m * I_ + nidx) = hi;
                *reinterpret_cast<__nv_bfloat162*>(g_xLo + (size_t)m * I_ + nidx) = lo;
            } else {
                int bb = m >> 9, tt = m & 511;
                float2 o; o.x = v0; o.y = v1;
                *reinterpret_cast<float2*>(
                    g_gx + ((size_t)tt * B_ + bb) * G4 + n) = o;
            }
        }
    }
}

// ---------------------------------------------------------------------------
// One LSTM step per launch. Blocks 0..127: (s=blk>>1, nb=blk&1) compute all
// 4 gates for hh slice [s*16,+16) x 32 batches, fused cell update in-block.
// Blocks 128,129: classifier rows; emit scores for step t-1 from the same h.
// ---------------------------------------------------------------------------
__device__ __forceinline__ float sigf(float x) { return 1.f / (1.f + expf(-x)); }

__global__ __launch_bounds__(256) void lstm_step(float* __restrict__ out,
                                                 const float* __restrict__ b_cls,
                                                 int t)
{
    const int blk = blockIdx.x;
    const bool is_cls = blk >= 128;
    if (is_cls ? (t < 1) : (t >= T_)) return;

    const int s  = is_cls ? 64 : (blk >> 1);
    const int nb = is_cls ? (blk - 128) : (blk & 1);
    const int tid = threadIdx.x, w = tid >> 5, lane = tid & 31;
    const int mw = w & 3, nw = w >> 2;
    const int r = lane >> 2, c = lane & 3;
    const int m0 = s * 64 + mw * 16;
    const int bb0 = nb * 32 + nw * 16;
    const int p = t & 1;

    const bf16* pAh = g_WrHi + (size_t)(m0 + r) * I_ + c * 8;
    const bf16* pAl = g_WrLo + (size_t)(m0 + r) * I_ + c * 8;
    const bf16* pBh = g_hHi[p] + (size_t)(bb0 + r) * I_ + c * 8;
    const bf16* pBl = g_hLo[p] + (size_t)(bb0 + r) * I_ + c * 8;
    const size_t A8 = (size_t)8 * I_;

    float acc[2][4];
#pragma unroll
    for (int j = 0; j < 2; j++)
#pragma unroll
        for (int q = 0; q < 4; q++) acc[j][q] = 0.f;

#pragma unroll 4
    for (int q = 0; q < I_ / 32; q++) {
        int off = q * 32;
        uint4 ah0 = *reinterpret_cast<const uint4*>(pAh + off);
        uint4 ah1 = *reinterpret_cast<const uint4*>(pAh + A8 + off);
        uint4 al0 = *reinterpret_cast<const uint4*>(pAl + off);
        uint4 al1 = *reinterpret_cast<const uint4*>(pAl + A8 + off);
#pragma unroll
        for (int j = 0; j < 2; j++) {
            uint4 bh = *reinterpret_cast<const uint4*>(pBh + (size_t)j * A8 + off);
            uint4 bl = *reinterpret_cast<const uint4*>(pBl + (size_t)j * A8 + off);
            SPLIT3(acc[j], ah0, ah1, al0, al1, bh, bl);
        }
    }

    if (is_cls) {
        int tq = t - 1;
#pragma unroll
        for (int j = 0; j < 2; j++) {
            int bA = bb0 + j * 8 + 2 * c;
            int row0 = mw * 16 + r, row1 = row0 + 8;
            if (row0 < NC) {
                float bc = b_cls[row0];
                out[((size_t)bA       * T_ + tq) * NC + row0] = acc[j][0] + bc;
                out[((size_t)(bA + 1) * T_ + tq) * NC + row0] = acc[j][1] + bc;
            }
            if (row1 < NC) {
                float bc = b_cls[row1];
                out[((size_t)bA       * T_ + tq) * NC + row1] = acc[j][2] + bc;
                out[((size_t)(bA + 1) * T_ + tq) * NC + row1] = acc[j][3] + bc;
            }
        }
        return;
    }

    __shared__ float Ds[64][33];
#pragma unroll
    for (int j = 0; j < 2; j++) {
        int col = nw * 16 + j * 8 + 2 * c;
        Ds[mw * 16 + r    ][col    ] = acc[j][0];
        Ds[mw * 16 + r    ][col + 1] = acc[j][1];
        Ds[mw * 16 + r + 8][col    ] = acc[j][2];
        Ds[mw * 16 + r + 8][col + 1] = acc[j][3];
    }
    __syncthreads();

    for (int e = tid; e < 512; e += 256) {
        int b = e >> 4, u = e & 15;
        int batch = nb * 32 + b;
        const float* gxp = g_gx + ((size_t)t * B_ + batch) * G4 + s * 16 + u;
        float gi = Ds[u][b]      + gxp[0];
        float gf = Ds[16 + u][b] + gxp[1024];
        float gg = Ds[32 + u][b] + gxp[2048];
        float go = Ds[48 + u][b] + gxp[3072];
        int cidx = batch * I_ + s * 16 + u;
        float cn = sigf(gf) * g_c[cidx] + sigf(gi) * tanhf(gg);
        g_c[cidx] = cn;
        float hv = sigf(go) * tanhf(cn);
        int k = s * 16 + u;
        int idx = (k & ~31) + perm32(k & 31);
        bf16 hi = __float2bfloat16(hv);
        g_hHi[(t + 1) & 1][(size_t)batch * I_ + idx] = hi;
        g_hLo[(t + 1) & 1][(size_t)batch * I_ + idx] =
            __float2bfloat16(hv - __bfloat162float(hi));
    }
}

// ---------------------------------------------------------------------------
extern "C" void kernel_launch(void* const* d_in, const int* in_sizes, int n_in,
                              void* d_out, int out_size)
{
    (void)in_sizes; (void)n_in; (void)out_size;
    const float* feat  = (const float*)d_in[0];
    const float* W_pre = (const float*)d_in[1];
    const float* b_pre = (const float*)d_in[2];
    const float* W_ih  = (const float*)d_in[3];
    const float* b_ih  = (const float*)d_in[4];
    const float* W_hh  = (const float*)d_in[5];
    const float* b_hh  = (const float*)d_in[6];
    const float* W_cls = (const float*)d_in[7];
    const float* b_cls = (const float*)d_in[8];
    float* out = (float*)d_out;

    prep_split<0><<<dim3(F_ / 512, M_), 256>>>(feat,  F_);
    prep_split<1><<<dim3(F_ / 512, I_), 256>>>(W_pre, F_);
    prep_split<2><<<dim3(I_ / 512, G4), 256>>>(W_ih,  I_);
    prep_rec     <<<dim3(I_ / 512, MP), 256>>>(W_hh, W_cls);
    init_state<<<(B_ * I_ + 255) / 256, 256>>>();

    // Phase 1: x = relu(feat @ W_pre^T + b_pre)      M=32768 N=1024 K=3072
    mma_gemm<F_, 0><<<dim3(I_ / 64, M_ / 64), 256>>>(b_pre, nullptr);
    // Phase 2: gx[t][b] = x @ W_ih^T + b_ih + b_hh   M=32768 N=4096 K=1024
    mma_gemm<I_, 1><<<dim3(G4 / 64, M_ / 64), 256>>>(b_ih, b_hh);

    // Phase 3: one fused kernel per step (513 launches; t=T_ emits last score)
    for (int t = 0; t <= T_; t++)
        lstm_step<<<130, 256>>>(out, b_cls, t);
}